// round 15
// baseline (speedup 1.0000x reference)
#include <cuda_runtime.h>
#include <cooperative_groups.h>

namespace cg = cooperative_groups;

#define BATCH 128
#define TSTEPS 2048
#define INDIM 32
#define HDIM 256
#define LDIM 16

#define CLS 8          // cluster size = CTAs per batch-group
#define TB 256         // threads per CTA (8 warps)

struct Smem {
    float hbuf[2][8][8][32];      // [buf][src rank][batch][lane]  16KB
    float4 scratch[2][8][8][32];  // [parity][kchunk][batch][col]  64KB
    float xbuf[2][8][32];         // [parity][batch][dim]           2KB
    float stage[8][32];           // my h rows (send source)        1KB
    unsigned long long mbars[24]; // [0..15] src[buf][rank]; [16..23] per-batch
};
#define SMEM_BYTES ((int)sizeof(Smem))

__device__ __forceinline__ unsigned long long pk2(float lo, float hi) {
    return ((unsigned long long)__float_as_uint(hi) << 32) |
           (unsigned long long)__float_as_uint(lo);
}
__device__ __forceinline__ float sum2(unsigned long long v) {
    return __uint_as_float((unsigned int)v) +
           __uint_as_float((unsigned int)(v >> 32));
}
#define FMA2(acc, w, h) \
    asm("fma.rn.f32x2 %0, %1, %2, %0;" : "+l"(acc) : "l"(w), "l"(h))

__device__ __forceinline__ unsigned smem_u32(const void* p) {
    unsigned r;
    asm("{ .reg .u64 t; cvta.to.shared.u64 t, %1; cvt.u32.u64 %0, t; }"
        : "=r"(r) : "l"(p));
    return r;
}
__device__ __forceinline__ float fast_sigmoid(float x) {
    return __fdividef(1.0f, 1.0f + __expf(-x));
}
__device__ __forceinline__ float fast_tanh(float x) {
    float ex = __expf(2.0f * x);
    return fmaf(-2.0f, __fdividef(1.0f, ex + 1.0f), 1.0f);
}
__device__ __forceinline__ void mbar_wait(unsigned addr, unsigned parity) {
    asm volatile(
        "{\n\t"
        ".reg .pred P;\n\t"
        "WL_%=:\n\t"
        "mbarrier.try_wait.parity.acquire.cta.shared::cta.b64 P, [%0], %1, 0x989680;\n\t"
        "@P bra.uni WD_%=;\n\t"
        "bra.uni WL_%=;\n\t"
        "WD_%=:\n\t"
        "}"
        :: "r"(addr), "r"(parity) : "memory");
}

__global__ void __cluster_dims__(CLS, 1, 1) __launch_bounds__(TB, 1)
gru_persistent_kernel(const float* __restrict__ xg,      // [B,T,IN]
                      const float* __restrict__ xl,      // [B,T,L]
                      const float* __restrict__ h0,      // [B,H]
                      const float* __restrict__ Wih,     // [3H,IN]
                      const float* __restrict__ Whh,     // [3H,H]
                      const float* __restrict__ bias,    // [3H]
                      const float* __restrict__ bias_n,  // [H]
                      float* __restrict__ out)           // [B,T,1]
{
    extern __shared__ __align__(16) char dynsmem[];
    Smem& sm = *reinterpret_cast<Smem*>(dynsmem);

    cg::cluster_group cluster = cg::this_cluster();
    const int rank = (int)cluster.block_rank();     // owns cols [32r, 32r+32)
    const int cid  = blockIdx.x / CLS;              // owns batches [8c, 8c+8)
    const int B0   = cid * 8;
    const int tid  = threadIdx.x;
    const int lane = tid & 31;
    const int warp = tid >> 5;      // FMA: consumes src slice 'warp'; gates: batch 'warp'
    const int col  = rank * 32 + lane;

    // ---- Weights in registers, packed (even k, odd k) ----
    unsigned long long wd[3][16];   // Whh[g][col][warp*32 .. +31]
    unsigned long long wi[3][2];    // Wih[g][col][warp*4 .. +3]
#pragma unroll
    for (int g = 0; g < 3; g++) {
        const float* wr = Whh + (size_t)(g * HDIM + col) * HDIM + warp * 32;
#pragma unroll
        for (int p = 0; p < 16; p++) wd[g][p] = pk2(wr[2 * p], wr[2 * p + 1]);
        const float* wx = Wih + (size_t)(g * HDIM + col) * INDIM + warp * 4;
        wi[g][0] = pk2(wx[0], wx[1]);
        wi[g][1] = pk2(wx[2], wx[3]);
    }
    const float b_r  = bias[col];
    const float b_z  = bias[HDIM + col];
    const float b_ni = bias[2 * HDIM + col];
    const float b_n2 = bias_n[col];

    const unsigned base  = smem_u32(&sm);
    const unsigned hoff  = smem_u32(&sm.hbuf[0][0][0][0]) - base;
    const unsigned soff  = smem_u32(&sm.stage[0][0]) - base;
    const unsigned mboff = smem_u32(&sm.mbars[0]) - base;
    const unsigned mloc  = base + mboff;

    if (tid == 0) {
#pragma unroll
        for (int i = 0; i < 16; i++)   // per-source tx barriers, count 1
            asm volatile("mbarrier.init.shared.b64 [%0], 1;"
                         :: "r"(mloc + i * 8) : "memory");
#pragma unroll
        for (int i = 16; i < 24; i++)  // per-batch barriers, count 8
            asm volatile("mbarrier.init.shared.b64 [%0], 8;"
                         :: "r"(mloc + i * 8) : "memory");
    }

    // ---- Init: buffer 0 holds full h0, laid out [src][batch][lane] ----
    for (int idx = tid; idx < 8 * HDIM; idx += TB) {
        int src = idx >> 8, b = (idx >> 5) & 7, l = idx & 31;
        sm.hbuf[0][src][b][l] = h0[(size_t)(B0 + b) * HDIM + src * 32 + l];
    }
    sm.xbuf[0][warp][lane] = xg[(size_t)(B0 + warp) * TSTEPS * INDIM + lane];

    float hreg = h0[(size_t)(B0 + warp) * HDIM + col];   // h_prev (batch B0+warp, col)
    float xl_reg = 0.f;
    if (rank == 0 && lane < LDIM)
        xl_reg = xl[(size_t)(B0 + warp) * TSTEPS * LDIM + lane];

    __syncthreads();
    cluster.sync();    // peers' mbarriers initialized before any bulk copy lands

    if (tid == 0) {
#pragma unroll
        for (int s = 0; s < 8; s++) {
            asm volatile("mbarrier.arrive.shared.b64 _, [%0];"
                         :: "r"(mloc + s * 8) : "memory");        // buf0 pre-filled
            asm volatile("mbarrier.arrive.expect_tx.shared.b64 _, [%0], %1;"
                         :: "r"(mloc + (8 + s) * 8), "r"(1024u) : "memory");
        }
    }

    unsigned peer = 0;
    if (lane < 8)   // every gate warp sends; lane -> rank (incl. self)
        asm("mapa.shared::cluster.u32 %0, %1, %2;" : "=r"(peer) : "r"(base), "r"(lane));

    for (int t = 0; t < TSTEPS; t++) {
        const int buf = t & 1;                          // hbuf parity (and scratch/xbuf)
        const unsigned spar = (unsigned)((t >> 1) & 1); // src-mbar parity
        const unsigned bpar = (unsigned)(t & 1);        // batch-mbar parity
        const int tn = (t + 1 < TSTEPS) ? t + 1 : t;
        const unsigned my_src = mloc + (unsigned)((buf * 8 + warp) * 8);

        mbar_wait(my_src, spar);   // only THIS warp's source slice must be local

        if (lane == 0 && t + 2 < TSTEPS)   // re-arm for t+2 (pre-arrive; proven safe)
            asm volatile("mbarrier.arrive.expect_tx.shared.b64 _, [%0], %1;"
                         :: "r"(my_src), "r"(1024u) : "memory");

        float xnext = xg[(size_t)(B0 + warp) * TSTEPS * INDIM +
                         (size_t)tn * INDIM + lane];

        // ---- Matvec partials, batch-rotated (own batch last), no block barrier ----
#pragma unroll
        for (int idx = 0; idx < 8; idx++) {
            const int b = (warp + 1 + idx) & 7;
            unsigned long long aR = 0ull, aZ = 0ull, aNh = 0ull, aNi = 0ull;

            ulonglong2 x2 = *reinterpret_cast<const ulonglong2*>(
                &sm.xbuf[buf][b][warp * 4]);
            FMA2(aR,  wi[0][0], x2.x); FMA2(aZ,  wi[1][0], x2.x);
            FMA2(aNi, wi[2][0], x2.x); FMA2(aR,  wi[0][1], x2.y);
            FMA2(aZ,  wi[1][1], x2.y); FMA2(aNi, wi[2][1], x2.y);

#pragma unroll
            for (int i = 0; i < 8; i++) {
                // broadcast LDS.128: all lanes read the same 16B of h
                ulonglong2 h2 = *reinterpret_cast<const ulonglong2*>(
                    &sm.hbuf[buf][warp][b][4 * i]);
                FMA2(aR,  wd[0][2 * i],     h2.x);
                FMA2(aZ,  wd[1][2 * i],     h2.x);
                FMA2(aNh, wd[2][2 * i],     h2.x);
                FMA2(aR,  wd[0][2 * i + 1], h2.y);
                FMA2(aZ,  wd[1][2 * i + 1], h2.y);
                FMA2(aNh, wd[2][2 * i + 1], h2.y);
            }
            sm.scratch[buf][warp][b][lane] =
                make_float4(sum2(aR), sum2(aZ), sum2(aNh), sum2(aNi));
            __syncwarp();
            if (lane == 0)   // release-arrive: my partial for batch b is visible
                asm volatile("mbarrier.arrive.shared.b64 _, [%0];"
                             :: "r"(mloc + (unsigned)((16 + b) * 8)) : "memory");
        }

        sm.xbuf[buf ^ 1][warp][lane] = xnext;   // parity buffer; readers at t+1

        // ---- Wait only for MY batch's 8 partials (acquire) ----
        mbar_wait(mloc + (unsigned)((16 + warp) * 8), bpar);

        // ---- Reduce + gates: thread = (batch=warp, col=lane) ----
        {
            float sR = 0.f, sZ = 0.f, sNh = 0.f, sNi = 0.f;
#pragma unroll
            for (int kc = 0; kc < 8; kc++) {
                float4 v = sm.scratch[buf][kc][warp][lane];
                sR += v.x; sZ += v.y; sNh += v.z; sNi += v.w;
            }
            const float r = fast_sigmoid(sR + b_r);
            const float z = fast_sigmoid(sZ + b_z);
            const float n = fast_tanh(sNi + b_ni + r * (sNh + b_n2));
            hreg = n + z * (hreg - n);
        }

        // ---- Send my 128B row to all 8 ranks (incl. self; completes src mbars) ----
        if (t + 1 < TSTEPS) {
            sm.stage[warp][lane] = hreg;
            __syncwarp();
            asm volatile("fence.proxy.async.shared::cta;" ::: "memory");
            if (lane < 8) {
                const unsigned src = base + soff + (unsigned)(warp * 128);
                const unsigned dst = peer + hoff +
                    (unsigned)((buf ^ 1) * 8192 + rank * 1024 + warp * 128);
                const unsigned dmb = peer + mboff +
                    (unsigned)(((buf ^ 1) * 8 + rank) * 8);
                asm volatile(
                    "cp.async.bulk.shared::cluster.shared::cta.mbarrier::complete_tx::bytes "
                    "[%0], [%1], %2, [%3];"
                    :: "r"(dst), "r"(src), "r"(128u), "r"(dmb) : "memory");
            }
        }

        // ---- Readout (columns 0..15 live in rank 0) ----
        if (rank == 0) {
            float prod = (lane < LDIM) ? hreg * xl_reg : 0.f;
#pragma unroll
            for (int o = 16; o; o >>= 1)
                prod += __shfl_xor_sync(0xffffffffu, prod, o);
            if (lane == 0) out[(size_t)(B0 + warp) * TSTEPS + t] = prod;
            if (lane < LDIM)
                xl_reg = xl[(size_t)(B0 + warp) * TSTEPS * LDIM +
                            (size_t)tn * LDIM + lane];
        }
    }

    cluster.sync();   // clean distributed exit
}

extern "C" void kernel_launch(void* const* d_in, const int* in_sizes, int n_in,
                              void* d_out, int out_size) {
    (void)in_sizes; (void)n_in; (void)out_size;
    const float* xg     = (const float*)d_in[0];  // input_gru   [128,2048,32]
    const float* xl     = (const float*)d_in[1];  // input_linear[128,2048,16]
    const float* h0     = (const float*)d_in[2];  // init_hidden [128,256]
    const float* Wih    = (const float*)d_in[3];  // [768,32]
    const float* Whh    = (const float*)d_in[4];  // [768,256]
    const float* bias   = (const float*)d_in[5];  // [768]
    const float* bias_n = (const float*)d_in[6];  // [256]
    float* out = (float*)d_out;                   // [128,2048,1]

    cudaFuncSetAttribute(gru_persistent_kernel,
                         cudaFuncAttributeMaxDynamicSharedMemorySize, SMEM_BYTES);

    gru_persistent_kernel<<<dim3(BATCH), dim3(TB), SMEM_BYTES>>>(
        xg, xl, h0, Wih, Whh, bias, bias_n, out);
}